// round 14
// baseline (speedup 1.0000x reference)
#include <cuda_runtime.h>
#include <cuda_bf16.h>
#include <math.h>

#define B_    128
#define Q_    16
#define QH    8                        // q's per CTA (Q split 2-way)
#define D_    1024
#define E_    300
#define K_    11
#define DOC_SPLIT 4
#define CTAS_PER_B 8                   // 4 doc-parts x 2 q-halves
#define DOCS_PER_CTA (D_/DOC_SPLIT)    // 256
#define THREADS1 128
#define E4    (E_/4)                   // 75 float4
#define QSTRIDE 304                    // floats (76 f4)
#define SSTRIDE 264                    // mod 32 == 8 -> conflict-free 8/16-lane groups

// partials: [B][16 q][4 docparts][13] (11 kacc + 1 simacc + pad)
__device__ float g_part[B_*Q_*DOC_SPLIT*13];
__device__ int   g_count[B_];          // zero-init; reset by last CTA each run

__global__ __launch_bounds__(THREADS1, 6)   // cap ~85 regs -> 6 CTAs/SM (24 warps)
void knrm_part_kernel(const int* __restrict__ doctoks,
                      const int* __restrict__ querytoks,
                      const float* __restrict__ emb,
                      const float* __restrict__ mus,
                      const float* __restrict__ sigmas,
                      const float* __restrict__ fc_w,
                      const float* __restrict__ fc_b,
                      float* __restrict__ out)
{
    __shared__ float sm[QH*QSTRIDE + 16];
    __shared__ int last_flag;
    float* qn    = sm;                // 8 x 304 ; later aliased as s_sh 8 x 264
    float* tmp8  = sm + QH*QSTRIDE;

    const int tid   = threadIdx.x;
    const int b     = blockIdx.x >> 3;
    const int sub   = blockIdx.x & 7;
    const int qhalf = sub >> 2;            // 0/1 : q rows [0,8) or [8,16)
    const int dc    = sub & 3;             // doc quarter
    const int qoff  = qhalf * QH;
    const int dbase = dc * DOCS_PER_CTA;

    // ---- load + normalize 8 query embeddings into shared ----
    for (int i = tid; i < QH*E_; i += THREADS1) {
        int q = i / E_, e = i - q*E_;
        int t = querytoks[b*Q_ + qoff + q];
        qn[q*QSTRIDE + e] = emb[t*E_ + e];
    }
    __syncthreads();
    {
        // 128 threads: 8 q-rows x 16 lanes each
        int q = tid >> 4, l = tid & 15;
        float ss = 0.f;
        for (int e = l; e < E_; e += 16) { float v = qn[q*QSTRIDE + e]; ss += v*v; }
        #pragma unroll
        for (int o = 8; o > 0; o >>= 1) ss += __shfl_down_sync(0xffffffffu, ss, o, 16);
        if (l == 0) tmp8[q] = 1.0f / (sqrtf(ss) + 1e-9f);
    }
    __syncthreads();
    for (int i = tid; i < QH*E_; i += THREADS1) {
        int q = i / E_, e = i - q*E_;
        qn[q*QSTRIDE + e] *= tmp8[q];
    }
    __syncthreads();

    // ---- dot products: 2 docs/thread, rolling prefetch depth 2 ----
    const int t0 = doctoks[b*D_ + dbase + tid];
    const int t1 = doctoks[b*D_ + dbase + tid + THREADS1];
    const float4* p0 = reinterpret_cast<const float4*>(emb) + (long)t0 * E4;
    const float4* p1 = reinterpret_cast<const float4*>(emb) + (long)t1 * E4;
    const float4* qn4 = reinterpret_cast<const float4*>(qn);

    float acc0[QH], acc1[QH];
    #pragma unroll
    for (int q = 0; q < QH; q++) { acc0[q] = 0.f; acc1[q] = 0.f; }
    float dd0 = 0.f, dd1 = 0.f;

    auto fmastep = [&](const float4 a, const float4 c, int e4) {
        dd0 = fmaf(a.x,a.x, fmaf(a.y,a.y, fmaf(a.z,a.z, fmaf(a.w,a.w, dd0))));
        dd1 = fmaf(c.x,c.x, fmaf(c.y,c.y, fmaf(c.z,c.z, fmaf(c.w,c.w, dd1))));
        #pragma unroll
        for (int q = 0; q < QH; q++) {
            float4 v = qn4[q*(QSTRIDE/4) + e4];
            acc0[q] = fmaf(a.x,v.x, fmaf(a.y,v.y, fmaf(a.z,v.z, fmaf(a.w,v.w, acc0[q]))));
            acc1[q] = fmaf(c.x,v.x, fmaf(c.y,v.y, fmaf(c.z,v.z, fmaf(c.w,v.w, acc1[q]))));
        }
    };

    // depth-2 rolling prefetch; main loop j<70 has j+2<=71 < 75 (no predicates)
    float4 a0 = p0[0], c0 = p1[0];
    float4 a1 = p0[1], c1 = p1[1];
    #pragma unroll 5
    for (int j = 0; j < 70; j++) {
        float4 an = p0[j+2];
        float4 cn = p1[j+2];
        fmastep(a0, c0, j);
        a0 = a1; c0 = c1; a1 = an; c1 = cn;
    }
    #pragma unroll
    for (int j = 70; j < E4; j++) {
        float4 an, cn;
        if (j + 2 < E4) { an = p0[j+2]; cn = p1[j+2]; }
        else            { an = make_float4(0.f,0.f,0.f,0.f); cn = an; }
        fmastep(a0, c0, j);
        a0 = a1; c0 = c1; a1 = an; c1 = cn;
    }

    const float inv0 = 1.0f / (sqrtf(dd0) + 1e-9f);
    const float inv1 = 1.0f / (sqrtf(dd1) + 1e-9f);

    // ---- transpose s into shared (aliases dead qn region) ----
    float* s_sh = sm;   // 8 x 264
    __syncthreads();    // all qn reads done
    #pragma unroll
    for (int q = 0; q < QH; q++) {
        s_sh[q*SSTRIDE + tid]            = acc0[q] * inv0;
        s_sh[q*SSTRIDE + tid + THREADS1] = acc1[q] * inv1;
    }
    __syncthreads();

    // ---- RBF bank: 16 threads per q, each covers 16 docs ----
    const int myq = tid >> 4, myl = tid & 15;
    float mu_r[K_], w_r[K_];
    #pragma unroll
    for (int k = 0; k < K_; k++) {
        mu_r[k] = mus[k];
        float sg = sigmas[k];
        w_r[k] = -0.5f/(sg*sg);
    }
    float kacc[K_];
    #pragma unroll
    for (int k = 0; k < K_; k++) kacc[k] = 0.f;
    float simacc = 0.f;

    #pragma unroll 4
    for (int j = myl; j < DOCS_PER_CTA; j += 16) {
        float s = s_sh[myq*SSTRIDE + j];
        simacc += s;
        #pragma unroll
        for (int k = 0; k < K_; k++) {
            float dif = s - mu_r[k];
            kacc[k] += __expf(w_r[k]*dif*dif);
        }
    }

    // reduce over the 16 lanes of this q-group (contiguous lanes)
    #pragma unroll
    for (int k = 0; k < K_; k++) {
        float v = kacc[k];
        #pragma unroll
        for (int o = 8; o > 0; o >>= 1) v += __shfl_down_sync(0xffffffffu, v, o, 16);
        kacc[k] = v;
    }
    {
        float v = simacc;
        #pragma unroll
        for (int o = 8; o > 0; o >>= 1) v += __shfl_down_sync(0xffffffffu, v, o, 16);
        simacc = v;
    }
    if (myl == 0) {
        float* dst = &g_part[(((b*Q_) + qoff + myq)*DOC_SPLIT + dc)*13];
        #pragma unroll
        for (int k = 0; k < K_; k++) dst[k] = kacc[k];
        dst[11] = simacc;
    }

    // ---- fused finalization: last of 8 CTAs for this batch scores ----
    __syncthreads();
    if (tid == 0) {
        __threadfence();                       // release our partials
        int old = atomicAdd(&g_count[b], 1);
        last_flag = (old == CTAS_PER_B - 1);
    }
    __syncthreads();
    if (!last_flag) return;

    if (tid < 32) {
        __threadfence();                       // acquire other CTAs' partials
        const int lane = tid;
        const int q = lane & 15;               // lanes 16-31 duplicate; masked below
        const bool active = (lane < 16);

        float kb[K_];
        #pragma unroll
        for (int k = 0; k < K_; k++) kb[k] = 0.f;
        float sim = 0.f;
        #pragma unroll
        for (int cc = 0; cc < DOC_SPLIT; cc++) {
            const float* src = &g_part[((b*Q_ + q)*DOC_SPLIT + cc)*13];
            #pragma unroll
            for (int k = 0; k < K_; k++) kb[k] += src[k];
            sim += src[11];
        }
        const bool m = (sim != 0.0f) && active;
        float score = fc_b[0];
        #pragma unroll
        for (int k = 0; k < K_; k++) {
            float v = m ? logf(kb[k] + 1e-6f) : 0.0f;
            #pragma unroll
            for (int o = 8; o > 0; o >>= 1) v += __shfl_down_sync(0xffffffffu, v, o, 16);
            score = fmaf(v, fc_w[k], score);
        }
        if (lane == 0) {
            out[b] = score;
            g_count[b] = 0;                    // reset for next run / replay
        }
    }
}

extern "C" void kernel_launch(void* const* d_in, const int* in_sizes, int n_in,
                              void* d_out, int out_size)
{
    const int*   doctoks   = (const int*)  d_in[0];
    const int*   querytoks = (const int*)  d_in[1];
    // d_in[2] = query_idf (unused)
    const float* emb       = (const float*)d_in[3];
    const float* mus       = (const float*)d_in[4];
    const float* sigmas    = (const float*)d_in[5];
    const float* fc_w      = (const float*)d_in[6];
    const float* fc_b      = (const float*)d_in[7];
    float* out = (float*)d_out;

    knrm_part_kernel<<<B_*CTAS_PER_B, THREADS1>>>(
        doctoks, querytoks, emb, mus, sigmas, fc_w, fc_b, out);
}